// round 16
// baseline (speedup 1.0000x reference)
#include <cuda_runtime.h>
#include <cuda_fp16.h>
#include <math.h>
#include <stdint.h>

#define BB 2
#define PP 4096
#define HID 1152
#define NH 16
#define HD 72
#define MTOT (BB*PP)            // 8192
#define LOG2E 1.44269504088896f

// ---------------- scratch (device globals; no allocations allowed) ----------
__device__ float g_q[(size_t)MTOT * HID];
__device__ float g_k[(size_t)MTOT * HID];
__device__ float g_v[(size_t)MTOT * HID];
__device__ __half g_hh[(size_t)MTOT * HID];   // hidden hi (reused for o hi)
__device__ __half g_hl[(size_t)MTOT * HID];   // hidden lo
__device__ __half g_qh[(size_t)MTOT * HID];
__device__ __half g_ql[(size_t)MTOT * HID];
__device__ __half g_kh[(size_t)MTOT * HID];
__device__ __half g_kl[(size_t)MTOT * HID];
__device__ __half g_vh[(size_t)MTOT * HID];
__device__ __half g_wqh[(size_t)HID * HID];
__device__ __half g_wql[(size_t)HID * HID];
__device__ __half g_wkh[(size_t)HID * HID];
__device__ __half g_wkl[(size_t)HID * HID];
__device__ __half g_wvh[(size_t)HID * HID];
__device__ __half g_woh[(size_t)HID * HID];
__device__ __half g_scr[(size_t)HID * HID];   // throwaway lo for 1-product weights

// ---------------- low-level helpers -----------------------------------------
__device__ __forceinline__ uint32_t smem_u32(const void* p) {
    uint32_t a;
    asm("{ .reg .u64 t; cvta.to.shared.u64 t, %1; cvt.u32.u64 %0, t; }"
        : "=r"(a) : "l"(p));
    return a;
}

__device__ __forceinline__ void mma16816(float* c, const uint32_t* a, const uint32_t* b) {
    asm volatile(
        "mma.sync.aligned.m16n8k16.row.col.f32.f16.f16.f32 "
        "{%0,%1,%2,%3}, {%4,%5,%6,%7}, {%8,%9}, {%0,%1,%2,%3};"
        : "+f"(c[0]), "+f"(c[1]), "+f"(c[2]), "+f"(c[3])
        : "r"(a[0]), "r"(a[1]), "r"(a[2]), "r"(a[3]), "r"(b[0]), "r"(b[1]));
}

__device__ __forceinline__ void mma16808(float* c, const uint32_t* a, uint32_t b) {
    asm volatile(
        "mma.sync.aligned.m16n8k8.row.col.f32.f16.f16.f32 "
        "{%0,%1,%2,%3}, {%4,%5}, {%6}, {%0,%1,%2,%3};"
        : "+f"(c[0]), "+f"(c[1]), "+f"(c[2]), "+f"(c[3])
        : "r"(a[0]), "r"(a[1]), "r"(b));
}

__device__ __forceinline__ void split2(float x0, float x1, uint32_t& h, uint32_t& l) {
    __half h0 = __float2half_rn(x0);
    __half h1 = __float2half_rn(x1);
    __half2 hv; hv.x = h0; hv.y = h1;
    __half2 lv = __floats2half2_rn(x0 - __half2float(h0), x1 - __half2float(h1));
    h = *(uint32_t*)&hv;
    l = *(uint32_t*)&lv;
}

__device__ __forceinline__ uint32_t pack_h2(float x0, float x1) {
    __half2 hv = __floats2half2_rn(x0, x1);
    return *(uint32_t*)&hv;
}

__device__ __forceinline__ void ldsm4(uint32_t* r, uint32_t a) {
    asm volatile("ldmatrix.sync.aligned.m8n8.x4.shared.b16 {%0,%1,%2,%3}, [%4];"
                 : "=r"(r[0]), "=r"(r[1]), "=r"(r[2]), "=r"(r[3]) : "r"(a));
}
__device__ __forceinline__ void ldsm2t(uint32_t* r, uint32_t a) {
    asm volatile("ldmatrix.sync.aligned.m8n8.x2.trans.shared.b16 {%0,%1}, [%2];"
                 : "=r"(r[0]), "=r"(r[1]) : "r"(a));
}
__device__ __forceinline__ void ldsm4t(uint32_t* r, uint32_t a) {
    asm volatile("ldmatrix.sync.aligned.m8n8.x4.trans.shared.b16 {%0,%1,%2,%3}, [%4];"
                 : "=r"(r[0]), "=r"(r[1]), "=r"(r[2]), "=r"(r[3]) : "r"(a));
}

__device__ __forceinline__ void cpa16(uint32_t dst, const void* src) {
    asm volatile("cp.async.cg.shared.global [%0], [%1], 16;" :: "r"(dst), "l"(src));
}
#define CP_COMMIT asm volatile("cp.async.commit_group;" ::: "memory")
#define CP_WAIT0 asm volatile("cp.async.wait_group 0;" ::: "memory")
#define CP_WAIT1 asm volatile("cp.async.wait_group 1;" ::: "memory")

// ---------------- split: fp32 -> fp16 hi/lo ----------------------------------
__global__ void split_kernel(const float* __restrict__ s, __half* __restrict__ h,
                             __half* __restrict__ l, int n4)
{
    int i = blockIdx.x * blockDim.x + threadIdx.x;
    if (i >= n4) return;
    float4 v = ((const float4*)s)[i];
    uint32_t h0, l0, h1, l1;
    split2(v.x, v.y, h0, l0);
    split2(v.z, v.w, h1, l1);
    ((uint32_t*)h)[i * 2]     = h0;
    ((uint32_t*)h)[i * 2 + 1] = h1;
    ((uint32_t*)l)[i * 2]     = l0;
    ((uint32_t*)l)[i * 2 + 1] = l1;
}

// fused 4-weight split: y selects (Wq, Wk, Wv, Wo)
__global__ void split4_kernel(const float* __restrict__ w0, const float* __restrict__ w1,
                              const float* __restrict__ w2, const float* __restrict__ w3,
                              __half* __restrict__ h0p, __half* __restrict__ h1p,
                              __half* __restrict__ h2p, __half* __restrict__ h3p,
                              __half* __restrict__ l0p, __half* __restrict__ l1p,
                              __half* __restrict__ l2p, __half* __restrict__ l3p,
                              int n4)
{
    int i = blockIdx.x * blockDim.x + threadIdx.x;
    if (i >= n4) return;
    int y = blockIdx.y;
    const float* s = (y == 0) ? w0 : (y == 1) ? w1 : (y == 2) ? w2 : w3;
    __half* h = (y == 0) ? h0p : (y == 1) ? h1p : (y == 2) ? h2p : h3p;
    __half* l = (y == 0) ? l0p : (y == 1) ? l1p : (y == 2) ? l2p : l3p;
    float4 v = ((const float4*)s)[i];
    uint32_t a0, b0, a1, b1;
    split2(v.x, v.y, a0, b0);
    split2(v.z, v.w, a1, b1);
    ((uint32_t*)h)[i * 2]     = a0;
    ((uint32_t*)h)[i * 2 + 1] = a1;
    ((uint32_t*)l)[i * 2]     = b0;
    ((uint32_t*)l)[i * 2 + 1] = b1;
}

// ============== 3-product MMA GEMM (QK projections), K-chunk 48 =============
// Stage: A hi+lo [128 rows][96B data, 112B stride] + B hi+lo [48][272B] = 54,784 B
#define G3_AH 0
#define G3_AL 14336
#define G3_BH 28672
#define G3_BL 41728
#define G3STAGE 54784
#define GEMM_SMEM (2*G3STAGE)

__device__ __forceinline__ void gemm_fill3(uint32_t sb, int s,
    const __half* __restrict__ aH, const __half* __restrict__ aL,
    const __half* __restrict__ bH, const __half* __restrict__ bL,
    int m0, int n0, int k0, int tid)
{
    uint32_t st = sb + s * G3STAGE;
#pragma unroll
    for (int rep = 0; rep < 3; rep++) {
        int i = tid + rep * 256;          // 0..767
        {   // A: 128 rows x 6 16B-chunks (hi+lo)
            int c = i >> 7, r = i & 127;
            uint32_t off = (uint32_t)(r * 112 + c * 16);
            size_t g = (size_t)(m0 + r) * HID + k0 + c * 8;
            cpa16(st + G3_AH + off, aH + g);
            cpa16(st + G3_AL + off, aL + g);
        }
        {   // B: 48 rows x 16 chunks (hi+lo)
            int r = i >> 4, c = i & 15;
            uint32_t off = (uint32_t)(r * 272 + c * 16);
            size_t g = (size_t)(k0 + r) * HID + n0 + c * 8;
            cpa16(st + G3_BH + off, bH + g);
            cpa16(st + G3_BL + off, bL + g);
        }
    }
}

__global__ __launch_bounds__(256, 2)
void mma_gemm_qk(const __half* __restrict__ aH, const __half* __restrict__ aL,
                 const __half* __restrict__ qWh, const __half* __restrict__ qWl,
                 const __half* __restrict__ kWh, const __half* __restrict__ kWl,
                 float* __restrict__ q, float* __restrict__ k)
{
    const __half* bH = (blockIdx.z == 0) ? qWh : kWh;
    const __half* bL = (blockIdx.z == 0) ? qWl : kWl;
    float* C = (blockIdx.z == 0) ? q : k;
    const int m0 = blockIdx.y * 128, n0 = blockIdx.x * 128;

    extern __shared__ char smem[];
    const uint32_t sb = smem_u32(smem);
    const int tid = threadIdx.x;
    const int lane = tid & 31;
    const int wid = tid >> 5;
    const int wm = wid & 3;
    const int wn = wid >> 2;
    const int g = lane >> 3, j = lane & 7;

    const uint32_t a4inv = (uint32_t)(((g & 1) * 8 + j) * 112 + (g >> 1) * 16);
    const uint32_t b4inv = (uint32_t)((lane & 15) * 272 + (lane >> 4) * 16);

    float c[2][8][4];
#pragma unroll
    for (int mt = 0; mt < 2; mt++)
#pragma unroll
        for (int nt = 0; nt < 8; nt++)
#pragma unroll
            for (int e = 0; e < 4; e++) c[mt][nt][e] = 0.f;

    gemm_fill3(sb, 0, aH, aL, bH, bL, m0, n0, 0, tid);
    CP_COMMIT;

    const int NCH = HID / 48;   // 24
    for (int ch = 0; ch < NCH; ch++) {
        const int s = ch & 1;
        if (ch + 1 < NCH) {
            gemm_fill3(sb, s ^ 1, aH, aL, bH, bL, m0, n0, (ch + 1) * 48, tid);
            CP_COMMIT;
            CP_WAIT1;
        } else {
            CP_WAIT0;
        }
        __syncthreads();

        const uint32_t aBh = sb + s * G3STAGE + G3_AH;
        const uint32_t aBl = sb + s * G3STAGE + G3_AL;
        const uint32_t bBh = sb + s * G3STAGE + G3_BH;
        const uint32_t bBl = sb + s * G3STAGE + G3_BL;

#pragma unroll
        for (int ks = 0; ks < 3; ks++) {
            uint32_t fah[2][4], fal[2][4];
#pragma unroll
            for (int mt = 0; mt < 2; mt++) {
                uint32_t ao = a4inv + (uint32_t)((wm * 32 + mt * 16) * 112 + ks * 32);
                ldsm4(fah[mt], aBh + ao);
                ldsm4(fal[mt], aBl + ao);
            }
#pragma unroll
            for (int ntp = 0; ntp < 4; ntp++) {
                uint32_t bo = b4inv + (uint32_t)(ks * 16 * 272
                                                 + (wn * 64 + ntp * 16) * 2);
                uint32_t fbh[4], fbl[4];
                ldsm4t(fbh, bBh + bo);
                ldsm4t(fbl, bBl + bo);
#pragma unroll
                for (int mt = 0; mt < 2; mt++) {
                    mma16816(c[mt][2 * ntp],     fah[mt], fbh);
                    mma16816(c[mt][2 * ntp + 1], fah[mt], fbh + 2);
                    mma16816(c[mt][2 * ntp],     fah[mt], fbl);
                    mma16816(c[mt][2 * ntp + 1], fah[mt], fbl + 2);
                    mma16816(c[mt][2 * ntp],     fal[mt], fbh);
                    mma16816(c[mt][2 * ntp + 1], fal[mt], fbh + 2);
                }
            }
        }
        __syncthreads();
    }

#pragma unroll
    for (int mt = 0; mt < 2; mt++) {
#pragma unroll
        for (int nt = 0; nt < 8; nt++) {
            int row = m0 + wm * 32 + mt * 16 + (lane >> 2);
            int col = n0 + wn * 64 + nt * 8 + (lane & 3) * 2;
            *(float2*)(C + (size_t)row * HID + col) =
                make_float2(c[mt][nt][0], c[mt][nt][1]);
            *(float2*)(C + (size_t)(row + 8) * HID + col) =
                make_float2(c[mt][nt][2], c[mt][nt][3]);
        }
    }
}

// ============== 1-product MMA GEMM (V/O projections), K-chunk 64 ============
#define G1_A 0
#define G1_B 18432
#define G1STAGE 35840
#define GEMM1_SMEM (2*G1STAGE)

__device__ __forceinline__ void gemm_fill1(uint32_t sb, int s,
    const __half* __restrict__ aH, const __half* __restrict__ bH,
    int m0, int n0, int k0, int tid)
{
    uint32_t st = sb + s * G1STAGE;
#pragma unroll
    for (int rep = 0; rep < 4; rep++) {
        int i = tid + rep * 256;          // 0..1023
        {   // A: 128 rows x 8 16B-chunks
            int r = i >> 3, c = i & 7;
            uint32_t off = (uint32_t)(r * 144 + c * 16);
            size_t g = (size_t)(m0 + r) * HID + k0 + c * 8;
            cpa16(st + G1_A + off, aH + g);
        }
        {   // B: 64 rows x 16 chunks
            int r = i >> 4, c = i & 15;
            uint32_t off = (uint32_t)(r * 272 + c * 16);
            size_t g = (size_t)(k0 + r) * HID + n0 + c * 8;
            cpa16(st + G1_B + off, bH + g);
        }
    }
}

__global__ __launch_bounds__(256, 2)
void mma_gemm_1p(const __half* __restrict__ aH,
                 const __half* __restrict__ wH,
                 float* __restrict__ C)
{
    const int m0 = blockIdx.y * 128, n0 = blockIdx.x * 128;
    extern __shared__ char smem[];
    const uint32_t sb = smem_u32(smem);
    const int tid = threadIdx.x;
    const int lane = tid & 31;
    const int wid = tid >> 5;
    const int wm = wid & 3;
    const int wn = wid >> 2;
    const int g = lane >> 3, j = lane & 7;

    const uint32_t a4inv = (uint32_t)(((g & 1) * 8 + j) * 144 + (g >> 1) * 16);
    const uint32_t b4inv = (uint32_t)((lane & 15) * 272 + (lane >> 4) * 16);

    float c[2][8][4];
#pragma unroll
    for (int mt = 0; mt < 2; mt++)
#pragma unroll
        for (int nt = 0; nt < 8; nt++)
#pragma unroll
            for (int e = 0; e < 4; e++) c[mt][nt][e] = 0.f;

    gemm_fill1(sb, 0, aH, wH, m0, n0, 0, tid);
    CP_COMMIT;

    const int NCH = HID / 64;   // 18
    for (int ch = 0; ch < NCH; ch++) {
        const int s = ch & 1;
        if (ch + 1 < NCH) {
            gemm_fill1(sb, s ^ 1, aH, wH, m0, n0, (ch + 1) * 64, tid);
            CP_COMMIT;
            CP_WAIT1;
        } else {
            CP_WAIT0;
        }
        __syncthreads();

        const uint32_t aB = sb + s * G1STAGE + G1_A;
        const uint32_t bB = sb + s * G1STAGE + G1_B;

#pragma unroll
        for (int ks = 0; ks < 4; ks++) {
            uint32_t fah[2][4];
#pragma unroll
            for (int mt = 0; mt < 2; mt++) {
                uint32_t ao = a4inv + (uint32_t)((wm * 32 + mt * 16) * 144 + ks * 32);
                ldsm4(fah[mt], aB + ao);
            }
#pragma unroll
            for (int ntp = 0; ntp < 4; ntp++) {
                uint32_t bo = b4inv + (uint32_t)(ks * 16 * 272
                                                 + (wn * 64 + ntp * 16) * 2);
                uint32_t fbh[4];
                ldsm4t(fbh, bB + bo);
#pragma unroll
                for (int mt = 0; mt < 2; mt++) {
                    mma16816(c[mt][2 * ntp],     fah[mt], fbh);
                    mma16816(c[mt][2 * ntp + 1], fah[mt], fbh + 2);
                }
            }
        }
        __syncthreads();
    }

#pragma unroll
    for (int mt = 0; mt < 2; mt++) {
#pragma unroll
        for (int nt = 0; nt < 8; nt++) {
            int row = m0 + wm * 32 + mt * 16 + (lane >> 2);
            int col = n0 + wn * 64 + nt * 8 + (lane & 3) * 2;
            *(float2*)(C + (size_t)row * HID + col) =
                make_float2(c[mt][nt][0], c[mt][nt][1]);
            *(float2*)(C + (size_t)(row + 8) * HID + col) =
                make_float2(c[mt][nt][2], c[mt][nt][3]);
        }
    }
}

// ------------- fused RMSNorm (+weight) + 2D RoPE + fp16 hi/lo split ---------
// q is additionally scaled by LOG2E so attention softmax can use exp2.
__global__ void norm_rope_split(const float* __restrict__ q, const float* __restrict__ k,
                                const float* __restrict__ v,
                                const float* __restrict__ cosb,
                                const float* __restrict__ sinb,
                                const float* __restrict__ qw,
                                const float* __restrict__ kw,
                                __half* __restrict__ qh, __half* __restrict__ ql,
                                __half* __restrict__ kh, __half* __restrict__ kl,
                                __half* __restrict__ vh)
{
    __shared__ float sm[8][HD];
    int warp = threadIdx.x >> 5;
    int lane = threadIdx.x & 31;
    int gid = blockIdx.x * 8 + warp;
    int bp = gid >> 4;
    int h  = gid & 15;
    size_t base  = (size_t)bp * HID + (size_t)h * HD;
    size_t cbase = (size_t)bp * HD;

    float c0 = cosb[cbase + lane],      s0 = sinb[cbase + lane];
    float c1 = cosb[cbase + 32 + lane], s1 = sinb[cbase + 32 + lane];
    float c2 = 0.f, s2 = 0.f;
    if (lane < 8) { c2 = cosb[cbase + 64 + lane]; s2 = sinb[cbase + 64 + lane]; }

#pragma unroll
    for (int t = 0; t < 2; t++) {
        const float* buf = (t == 0) ? q : k;
        const float* w = (t == 0) ? qw : kw;
        __half* oh = (t == 0) ? qh : kh;
        __half* ol = (t == 0) ? ql : kl;
        const float osc = (t == 0) ? LOG2E : 1.0f;
        float x0 = buf[base + lane];
        float x1 = buf[base + 32 + lane];
        float x2 = (lane < 8) ? buf[base + 64 + lane] : 0.f;
        float ss = x0 * x0 + x1 * x1 + x2 * x2;
#pragma unroll
        for (int m = 16; m; m >>= 1) ss += __shfl_xor_sync(0xffffffffu, ss, m);
        float r = rsqrtf(ss * (1.0f / 72.0f) + 1e-6f);
        sm[warp][lane]      = x0 * r * w[lane];
        sm[warp][lane + 32] = x1 * r * w[lane + 32];
        if (lane < 8) sm[warp][lane + 64] = x2 * r * w[lane + 64];
        __syncwarp();
        {
            int d = lane;
            int jj = (d < 36) ? d : d - 36;
            float rh = (jj < 18) ? -sm[warp][d + 18] : sm[warp][d - 18];
            float out = (sm[warp][d] * c0 + rh * s0) * osc;
            __half hh = __float2half_rn(out);
            oh[base + d] = hh;
            ol[base + d] = __float2half_rn(out - __half2float(hh));
        }
        {
            int d = lane + 32;
            int jj = (d < 36) ? d : d - 36;
            float rh = (jj < 18) ? -sm[warp][d + 18] : sm[warp][d - 18];
            float out = (sm[warp][d] * c1 + rh * s1) * osc;
            __half hh = __float2half_rn(out);
            oh[base + d] = hh;
            ol[base + d] = __float2half_rn(out - __half2float(hh));
        }
        if (lane < 8) {
            int d = lane + 64;
            int jj = d - 36;
            float rh = (jj < 18) ? -sm[warp][d + 18] : sm[warp][d - 18];
            float out = (sm[warp][d] * c2 + rh * s2) * osc;
            __half hh = __float2half_rn(out);
            oh[base + d] = hh;
            ol[base + d] = __float2half_rn(out - __half2float(hh));
        }
        __syncwarp();
    }
    {
        float x0 = v[base + lane];
        float x1 = v[base + 32 + lane];
        float x2 = (lane < 8) ? v[base + 64 + lane] : 0.f;
        float ss = x0 * x0 + x1 * x1 + x2 * x2;
#pragma unroll
        for (int m = 16; m; m >>= 1) ss += __shfl_xor_sync(0xffffffffu, ss, m);
        float r = rsqrtf(ss * (1.0f / 72.0f) + 1e-6f);
        vh[base + lane]      = __float2half_rn(x0 * r);
        vh[base + 32 + lane] = __float2half_rn(x1 * r);
        if (lane < 8) vh[base + 64 + lane] = __float2half_rn(x2 * r);
    }
}

// ---------------- pipelined flash attention (mma.sync fp16) -----------------
// S is in log2 domain (q pre-scaled by LOG2E) -> softmax uses exp2f.
// QK: fp16x3 with fused tail. PV: P_hi x V_hi.
// 3-stage cp.async, ONE __syncthreads per tile.
#define AOFF_KH 0
#define AOFF_KL 11264
#define AOFF_VH 22528
#define ASTAGE  31744
#define ATTN_SMEM (3*ASTAGE)

__device__ __forceinline__ void attn_fill(uint32_t sb, int s,
    const __half* __restrict__ kh, const __half* __restrict__ kl,
    const __half* __restrict__ vh,
    size_t kb, size_t hoff, int tid)
{
    uint32_t st = sb + s * ASTAGE;
    for (int i = tid; i < 576; i += 256) {
        int r = i / 9, c = i - r * 9;
        size_t g = (kb + r) * HID + hoff + c * 8;
        uint32_t ko = (uint32_t)(r * 176 + c * 16);
        uint32_t vo = (uint32_t)(r * 144 + c * 16);
        cpa16(st + AOFF_KH + ko, kh + g);
        cpa16(st + AOFF_KL + ko, kl + g);
        cpa16(st + AOFF_VH + vo, vh + g);
    }
}

__global__ __launch_bounds__(256, 2)
void attn_mma(const __half* __restrict__ qh, const __half* __restrict__ ql,
              const __half* __restrict__ kh, const __half* __restrict__ kl,
              const __half* __restrict__ vh,
              __half* __restrict__ oh)
{
    extern __shared__ char smem[];
    const uint32_t sb = smem_u32(smem);
    const int tid = threadIdx.x;
    const int lane = tid & 31;
    const int wid = tid >> 5;
    const int b = blockIdx.z, h = blockIdx.y;
    const int q0 = blockIdx.x * 128;
    const size_t rowbase = (size_t)b * PP;
    const size_t hoff = (size_t)h * HD;

    attn_fill(sb, 0, kh, kl, vh, rowbase, hoff, tid);
    CP_COMMIT;
    attn_fill(sb, 1, kh, kl, vh, rowbase + 64, hoff, tid);
    CP_COMMIT;

    const int lg = lane >> 3, lj = lane & 7;
    const uint32_t k4inv = (uint32_t)(((lg >> 1) * 8 + lj) * 176 + (lg & 1) * 16);
    const uint32_t kt4inv = (uint32_t)((lg * 8 + lj) * 176 + 128);
    const uint32_t vinv  = (uint32_t)((lane & 15) * 144 + (lane >> 4) * 16);
    const uint32_t v2inv = (uint32_t)((lane & 15) * 144);

    uint32_t qfh[4][4], qfl[4][4], qt[4];
    {
        int ra = q0 + wid * 16 + (lane >> 2);
        const size_t ga = (rowbase + ra) * HID + hoff;
        const size_t gb = ga + (size_t)8 * HID;
        const int kof = (lane & 3) * 2;
#pragma unroll
        for (int ks = 0; ks < 4; ks++) {
            int kk = ks * 16 + kof;
            qfh[ks][0] = *(const uint32_t*)(qh + ga + kk);
            qfh[ks][1] = *(const uint32_t*)(qh + gb + kk);
            qfh[ks][2] = *(const uint32_t*)(qh + ga + kk + 8);
            qfh[ks][3] = *(const uint32_t*)(qh + gb + kk + 8);
            qfl[ks][0] = *(const uint32_t*)(ql + ga + kk);
            qfl[ks][1] = *(const uint32_t*)(ql + gb + kk);
            qfl[ks][2] = *(const uint32_t*)(ql + ga + kk + 8);
            qfl[ks][3] = *(const uint32_t*)(ql + gb + kk + 8);
        }
        qt[0] = *(const uint32_t*)(qh + ga + 64 + kof);
        qt[1] = *(const uint32_t*)(qh + gb + 64 + kof);
        qt[2] = *(const uint32_t*)(ql + ga + 64 + kof);
        qt[3] = *(const uint32_t*)(ql + gb + 64 + kof);
    }

    float m0 = -1e30f, m1 = -1e30f, l0 = 0.f, l1 = 0.f;
    float oacc[9][4];
#pragma unroll
    for (int dt = 0; dt < 9; dt++)
#pragma unroll
        for (int e = 0; e < 4; e++) oacc[dt][e] = 0.f;

    int scur = 0, snext = 2;
    const int NT = PP / 64;      // 64
    for (int kt = 0; kt < NT; kt++) {
        if (kt + 1 < NT) { CP_WAIT1; } else { CP_WAIT0; }
        __syncthreads();
        if (kt + 2 < NT) {
            attn_fill(sb, snext, kh, kl, vh,
                      rowbase + (size_t)(kt + 2) * 64, hoff, tid);
            CP_COMMIT;
        }

        const uint32_t kBh = sb + scur * ASTAGE + AOFF_KH;
        const uint32_t kBl = sb + scur * ASTAGE + AOFF_KL;
        const uint32_t vBh = sb + scur * ASTAGE + AOFF_VH;
        scur = (scur == 2) ? 0 : scur + 1;
        snext = (snext == 2) ? 0 : snext + 1;

        float sv[8][4];
#pragma unroll
        for (int nt = 0; nt < 8; nt++)
#pragma unroll
            for (int e = 0; e < 4; e++) sv[nt][e] = 0.f;

#pragma unroll
        for (int ks = 0; ks < 4; ks++) {
#pragma unroll
            for (int ntp = 0; ntp < 4; ntp++) {
                uint32_t off = k4inv + (uint32_t)(ntp * 16 * 176 + ks * 32);
                uint32_t fbh[4], fbl[4];
                ldsm4(fbh, kBh + off);
                ldsm4(fbl, kBl + off);
                mma16816(sv[2 * ntp],     qfh[ks], fbh);
                mma16816(sv[2 * ntp + 1], qfh[ks], fbh + 2);
                mma16816(sv[2 * ntp],     qfh[ks], fbl);
                mma16816(sv[2 * ntp + 1], qfh[ks], fbl + 2);
                mma16816(sv[2 * ntp],     qfl[ks], fbh);
                mma16816(sv[2 * ntp + 1], qfl[ks], fbh + 2);
            }
        }
#pragma unroll
        for (int nt0 = 0; nt0 < 8; nt0 += 4) {
            uint32_t off = kt4inv + (uint32_t)(nt0 * 8 * 176);
            uint32_t bh[4], bl[4];
            ldsm4(bh, kBh + off);
            ldsm4(bl, kBl + off);
#pragma unroll
            for (int i = 0; i < 4; i++) {
                uint32_t bb[2] = { bh[i], bh[i] };
                mma16816(sv[nt0 + i], qt, bb);
                mma16808(sv[nt0 + i], qt, bl[i]);
            }
        }

        float mx0 = -1e30f, mx1 = -1e30f;
#pragma unroll
        for (int nt = 0; nt < 8; nt++) {
            mx0 = fmaxf(mx0, fmaxf(sv[nt][0], sv[nt][1]));
            mx1 = fmaxf(mx1, fmaxf(sv[nt][2], sv[nt][3]));
        }
        mx0 = fmaxf(mx0, __shfl_xor_sync(0xffffffffu, mx0, 1));
        mx0 = fmaxf(mx0, __shfl_xor_sync(0xffffffffu, mx0, 2));
        mx1 = fmaxf(mx1, __shfl_xor_sync(0xffffffffu, mx1, 1));
        mx1 = fmaxf(mx1, __shfl_xor_sync(0xffffffffu, mx1, 2));
        float nm0 = fmaxf(m0, mx0), nm1 = fmaxf(m1, mx1);
        uint32_t changed = __ballot_sync(0xffffffffu,
                                         (nm0 != m0) || (nm1 != m1));
        float rs0 = 0.f, rs1 = 0.f;
#pragma unroll
        for (int nt = 0; nt < 8; nt++) {
            sv[nt][0] = exp2f(sv[nt][0] - nm0);
            sv[nt][1] = exp2f(sv[nt][1] - nm0);
            sv[nt][2] = exp2f(sv[nt][2] - nm1);
            sv[nt][3] = exp2f(sv[nt][3] - nm1);
            rs0 += sv[nt][0] + sv[nt][1];
            rs1 += sv[nt][2] + sv[nt][3];
        }
        if (changed) {
            float a0 = exp2f(m0 - nm0), a1 = exp2f(m1 - nm1);
            l0 = l0 * a0 + rs0;
            l1 = l1 * a1 + rs1;
#pragma unroll
            for (int dt = 0; dt < 9; dt++) {
                oacc[dt][0] *= a0; oacc[dt][1] *= a0;
                oacc[dt][2] *= a1; oacc[dt][3] *= a1;
            }
        } else {
            l0 += rs0;
            l1 += rs1;
        }
        m0 = nm0; m1 = nm1;

#pragma unroll
        for (int pk = 0; pk < 4; pk++) {
            uint32_t aph[4];
            aph[0] = pack_h2(sv[2 * pk][0],     sv[2 * pk][1]);
            aph[1] = pack_h2(sv[2 * pk][2],     sv[2 * pk][3]);
            aph[2] = pack_h2(sv[2 * pk + 1][0], sv[2 * pk + 1][1]);
            aph[3] = pack_h2(sv[2 * pk + 1][2], sv[2 * pk + 1][3]);
            const uint32_t rowoff = (uint32_t)(pk * 16 * 144);
#pragma unroll
            for (int dtp = 0; dtp < 4; dtp++) {
                uint32_t off = vinv + rowoff + (uint32_t)(dtp * 32);
                uint32_t fh[4];
                ldsm4t(fh, vBh + off);
                mma16816(oacc[2 * dtp],     aph, fh);
                mma16816(oacc[2 * dtp + 1], aph, fh + 2);
            }
            {
                uint32_t off = v2inv + rowoff + 128;
                uint32_t fh2[2];
                ldsm2t(fh2, vBh + off);
                mma16816(oacc[8], aph, fh2);
            }
        }
    }

    l0 += __shfl_xor_sync(0xffffffffu, l0, 1);
    l0 += __shfl_xor_sync(0xffffffffu, l0, 2);
    l1 += __shfl_xor_sync(0xffffffffu, l1, 1);
    l1 += __shfl_xor_sync(0xffffffffu, l1, 2);
    float il0 = 1.0f / l0, il1 = 1.0f / l1;
    int ra = q0 + wid * 16 + (lane >> 2);
    size_t ga = (rowbase + ra) * HID + hoff + (lane & 3) * 2;
    size_t gb = ga + (size_t)8 * HID;
#pragma unroll
    for (int dt = 0; dt < 9; dt++) {
        *(uint32_t*)(oh + ga + dt * 8) =
            pack_h2(oacc[dt][0] * il0, oacc[dt][1] * il0);
        *(uint32_t*)(oh + gb + dt * 8) =
            pack_h2(oacc[dt][2] * il1, oacc[dt][3] * il1);
    }
}

// ---------------------------------- launch ----------------------------------
extern "C" void kernel_launch(void* const* d_in, const int* in_sizes, int n_in,
                              void* d_out, int out_size)
{
    const float* hidden = (const float*)d_in[0];
    const float* cosb   = (const float*)d_in[1];
    const float* sinb   = (const float*)d_in[2];
    const float* Wq     = (const float*)d_in[3];
    const float* Wk     = (const float*)d_in[4];
    const float* Wv     = (const float*)d_in[5];
    const float* Wo     = (const float*)d_in[6];
    const float* qw     = (const float*)d_in[7];
    const float* kw     = (const float*)d_in[8];
    float* out = (float*)d_out;

    float *q, *k, *v;
    __half *hh, *hl, *qh, *ql, *kh, *kl, *vh;
    __half *wqh, *wql, *wkh, *wkl, *wvh, *woh, *scr;
    cudaGetSymbolAddress((void**)&q, g_q);
    cudaGetSymbolAddress((void**)&k, g_k);
    cudaGetSymbolAddress((void**)&v, g_v);
    cudaGetSymbolAddress((void**)&hh, g_hh);
    cudaGetSymbolAddress((void**)&hl, g_hl);
    cudaGetSymbolAddress((void**)&qh, g_qh);
    cudaGetSymbolAddress((void**)&ql, g_ql);
    cudaGetSymbolAddress((void**)&kh, g_kh);
    cudaGetSymbolAddress((void**)&kl, g_kl);
    cudaGetSymbolAddress((void**)&vh, g_vh);
    cudaGetSymbolAddress((void**)&wqh, g_wqh);
    cudaGetSymbolAddress((void**)&wql, g_wql);
    cudaGetSymbolAddress((void**)&wkh, g_wkh);
    cudaGetSymbolAddress((void**)&wkl, g_wkl);
    cudaGetSymbolAddress((void**)&wvh, g_wvh);
    cudaGetSymbolAddress((void**)&woh, g_woh);
    cudaGetSymbolAddress((void**)&scr, g_scr);

    cudaFuncSetAttribute(mma_gemm_qk, cudaFuncAttributeMaxDynamicSharedMemorySize,
                         GEMM_SMEM);
    cudaFuncSetAttribute(mma_gemm_1p, cudaFuncAttributeMaxDynamicSharedMemorySize,
                         GEMM1_SMEM);
    cudaFuncSetAttribute(attn_mma, cudaFuncAttributeMaxDynamicSharedMemorySize,
                         ATTN_SMEM);

    const int NH4 = (MTOT * HID) / 4;
    const int NW4 = (HID * HID) / 4;

    split_kernel<<<NH4 / 256, 256>>>(hidden, hh, hl, NH4);
    dim3 wsgrid(NW4 / 256, 4);
    split4_kernel<<<wsgrid, 256>>>(Wq, Wk, Wv, Wo,
                                   wqh, wkh, wvh, woh,
                                   wql, wkl, scr, scr, NW4);

    dim3 qkgrid(HID / 128, MTOT / 128, 2);
    mma_gemm_qk<<<qkgrid, 256, GEMM_SMEM>>>(hh, hl, wqh, wql, wkh, wkl, q, k);

    dim3 vgrid(HID / 128, MTOT / 128);
    mma_gemm_1p<<<vgrid, 256, GEMM1_SMEM>>>(hh, wvh, v);

    norm_rope_split<<<(BB * PP * NH) / 8, 256>>>(q, k, v, cosb, sinb, qw, kw,
                                                 qh, ql, kh, kl, vh);

    dim3 agrid(PP / 128, NH, BB);
    attn_mma<<<agrid, 256, ATTN_SMEM>>>(qh, ql, kh, kl, vh, hh);

    dim3 ogrid(HID / 128, MTOT / 128);
    mma_gemm_1p<<<ogrid, 256, GEMM1_SMEM>>>(hh, woh, out);
}

// round 17
// speedup vs baseline: 1.0506x; 1.0506x over previous
#include <cuda_runtime.h>
#include <cuda_fp16.h>
#include <math.h>
#include <stdint.h>

#define BB 2
#define PP 4096
#define HID 1152
#define NH 16
#define HD 72
#define MTOT (BB*PP)            // 8192
#define LOG2E 1.44269504088896f

// ---------------- scratch (device globals; no allocations allowed) ----------
__device__ float g_q[(size_t)MTOT * HID];
__device__ float g_k[(size_t)MTOT * HID];
__device__ float g_v[(size_t)MTOT * HID];
__device__ __half g_hh[(size_t)MTOT * HID];   // hidden hi (reused for o hi)
__device__ __half g_hl[(size_t)MTOT * HID];   // hidden lo
__device__ __half g_qh[(size_t)MTOT * HID];
__device__ __half g_ql[(size_t)MTOT * HID];
__device__ __half g_kh[(size_t)MTOT * HID];
__device__ __half g_kl[(size_t)MTOT * HID];
__device__ __half g_vh[(size_t)MTOT * HID];
__device__ __half g_wqh[(size_t)HID * HID];
__device__ __half g_wql[(size_t)HID * HID];
__device__ __half g_wkh[(size_t)HID * HID];
__device__ __half g_wkl[(size_t)HID * HID];
__device__ __half g_wvh[(size_t)HID * HID];
__device__ __half g_woh[(size_t)HID * HID];
__device__ __half g_scr[(size_t)HID * HID];   // throwaway lo for 1-product weights

// ---------------- low-level helpers -----------------------------------------
__device__ __forceinline__ uint32_t smem_u32(const void* p) {
    uint32_t a;
    asm("{ .reg .u64 t; cvta.to.shared.u64 t, %1; cvt.u32.u64 %0, t; }"
        : "=r"(a) : "l"(p));
    return a;
}

__device__ __forceinline__ void mma16816(float* c, const uint32_t* a, const uint32_t* b) {
    asm volatile(
        "mma.sync.aligned.m16n8k16.row.col.f32.f16.f16.f32 "
        "{%0,%1,%2,%3}, {%4,%5,%6,%7}, {%8,%9}, {%0,%1,%2,%3};"
        : "+f"(c[0]), "+f"(c[1]), "+f"(c[2]), "+f"(c[3])
        : "r"(a[0]), "r"(a[1]), "r"(a[2]), "r"(a[3]), "r"(b[0]), "r"(b[1]));
}

__device__ __forceinline__ void mma16808(float* c, const uint32_t* a, uint32_t b) {
    asm volatile(
        "mma.sync.aligned.m16n8k8.row.col.f32.f16.f16.f32 "
        "{%0,%1,%2,%3}, {%4,%5}, {%6}, {%0,%1,%2,%3};"
        : "+f"(c[0]), "+f"(c[1]), "+f"(c[2]), "+f"(c[3])
        : "r"(a[0]), "r"(a[1]), "r"(b));
}

__device__ __forceinline__ void split2(float x0, float x1, uint32_t& h, uint32_t& l) {
    __half h0 = __float2half_rn(x0);
    __half h1 = __float2half_rn(x1);
    __half2 hv; hv.x = h0; hv.y = h1;
    __half2 lv = __floats2half2_rn(x0 - __half2float(h0), x1 - __half2float(h1));
    h = *(uint32_t*)&hv;
    l = *(uint32_t*)&lv;
}

__device__ __forceinline__ uint32_t pack_h2(float x0, float x1) {
    __half2 hv = __floats2half2_rn(x0, x1);
    return *(uint32_t*)&hv;
}

__device__ __forceinline__ void ldsm4(uint32_t* r, uint32_t a) {
    asm volatile("ldmatrix.sync.aligned.m8n8.x4.shared.b16 {%0,%1,%2,%3}, [%4];"
                 : "=r"(r[0]), "=r"(r[1]), "=r"(r[2]), "=r"(r[3]) : "r"(a));
}
__device__ __forceinline__ void ldsm2t(uint32_t* r, uint32_t a) {
    asm volatile("ldmatrix.sync.aligned.m8n8.x2.trans.shared.b16 {%0,%1}, [%2];"
                 : "=r"(r[0]), "=r"(r[1]) : "r"(a));
}
__device__ __forceinline__ void ldsm4t(uint32_t* r, uint32_t a) {
    asm volatile("ldmatrix.sync.aligned.m8n8.x4.trans.shared.b16 {%0,%1,%2,%3}, [%4];"
                 : "=r"(r[0]), "=r"(r[1]), "=r"(r[2]), "=r"(r[3]) : "r"(a));
}

__device__ __forceinline__ void cpa16(uint32_t dst, const void* src) {
    asm volatile("cp.async.cg.shared.global [%0], [%1], 16;" :: "r"(dst), "l"(src));
}
#define CP_COMMIT asm volatile("cp.async.commit_group;" ::: "memory")
#define CP_WAIT0 asm volatile("cp.async.wait_group 0;" ::: "memory")
#define CP_WAIT1 asm volatile("cp.async.wait_group 1;" ::: "memory")

// ---------------- split: fp32 -> fp16 hi/lo ----------------------------------
__global__ void split_kernel(const float* __restrict__ s, __half* __restrict__ h,
                             __half* __restrict__ l, int n4)
{
    int i = blockIdx.x * blockDim.x + threadIdx.x;
    if (i >= n4) return;
    float4 v = ((const float4*)s)[i];
    uint32_t h0, l0, h1, l1;
    split2(v.x, v.y, h0, l0);
    split2(v.z, v.w, h1, l1);
    ((uint32_t*)h)[i * 2]     = h0;
    ((uint32_t*)h)[i * 2 + 1] = h1;
    ((uint32_t*)l)[i * 2]     = l0;
    ((uint32_t*)l)[i * 2 + 1] = l1;
}

// fused 4-weight split: y selects (Wq, Wk, Wv, Wo)
__global__ void split4_kernel(const float* __restrict__ w0, const float* __restrict__ w1,
                              const float* __restrict__ w2, const float* __restrict__ w3,
                              __half* __restrict__ h0p, __half* __restrict__ h1p,
                              __half* __restrict__ h2p, __half* __restrict__ h3p,
                              __half* __restrict__ l0p, __half* __restrict__ l1p,
                              __half* __restrict__ l2p, __half* __restrict__ l3p,
                              int n4)
{
    int i = blockIdx.x * blockDim.x + threadIdx.x;
    if (i >= n4) return;
    int y = blockIdx.y;
    const float* s = (y == 0) ? w0 : (y == 1) ? w1 : (y == 2) ? w2 : w3;
    __half* h = (y == 0) ? h0p : (y == 1) ? h1p : (y == 2) ? h2p : h3p;
    __half* l = (y == 0) ? l0p : (y == 1) ? l1p : (y == 2) ? l2p : l3p;
    float4 v = ((const float4*)s)[i];
    uint32_t a0, b0, a1, b1;
    split2(v.x, v.y, a0, b0);
    split2(v.z, v.w, a1, b1);
    ((uint32_t*)h)[i * 2]     = a0;
    ((uint32_t*)h)[i * 2 + 1] = a1;
    ((uint32_t*)l)[i * 2]     = b0;
    ((uint32_t*)l)[i * 2 + 1] = b1;
}

// ============== 3-product MMA GEMM (QK projections), K-chunk 32 =============
#define GOFF_AH 0
#define GOFF_AL 10240
#define GOFF_BH 20480
#define GOFF_BL 29184
#define GSTAGE  37888
#define GEMM_SMEM (2*GSTAGE)

__device__ __forceinline__ void gemm_fill3(uint32_t sb, int s,
    const __half* __restrict__ aH, const __half* __restrict__ aL,
    const __half* __restrict__ bH, const __half* __restrict__ bL,
    int m0, int n0, int k0, int tid)
{
    uint32_t st = sb + s * GSTAGE;
#pragma unroll
    for (int rep = 0; rep < 2; rep++) {
        int i = tid + rep * 256;
        {
            int r = i >> 2, c = i & 3;
            uint32_t off = (uint32_t)(r * 80 + c * 16);
            size_t g = (size_t)(m0 + r) * HID + k0 + c * 8;
            cpa16(st + GOFF_AH + off, aH + g);
            cpa16(st + GOFF_AL + off, aL + g);
        }
        {
            int r = i >> 4, c = i & 15;
            uint32_t off = (uint32_t)(r * 272 + c * 16);
            size_t g = (size_t)(k0 + r) * HID + n0 + c * 8;
            cpa16(st + GOFF_BH + off, bH + g);
            cpa16(st + GOFF_BL + off, bL + g);
        }
    }
}

__global__ __launch_bounds__(256, 2)
void mma_gemm_qk(const __half* __restrict__ aH, const __half* __restrict__ aL,
                 const __half* __restrict__ qWh, const __half* __restrict__ qWl,
                 const __half* __restrict__ kWh, const __half* __restrict__ kWl,
                 float* __restrict__ q, float* __restrict__ k)
{
    const __half* bH = (blockIdx.z == 0) ? qWh : kWh;
    const __half* bL = (blockIdx.z == 0) ? qWl : kWl;
    float* C = (blockIdx.z == 0) ? q : k;
    const int m0 = blockIdx.y * 128, n0 = blockIdx.x * 128;

    extern __shared__ char smem[];
    const uint32_t sb = smem_u32(smem);
    const int tid = threadIdx.x;
    const int lane = tid & 31;
    const int wid = tid >> 5;
    const int wm = wid & 3;
    const int wn = wid >> 2;
    const int g = lane >> 3, j = lane & 7;

    const uint32_t a4inv = (uint32_t)(((g & 1) * 8 + j) * 80 + (g >> 1) * 16);
    const uint32_t b4inv = (uint32_t)((lane & 15) * 272 + (lane >> 4) * 16);

    float c[2][8][4];
#pragma unroll
    for (int mt = 0; mt < 2; mt++)
#pragma unroll
        for (int nt = 0; nt < 8; nt++)
#pragma unroll
            for (int e = 0; e < 4; e++) c[mt][nt][e] = 0.f;

    gemm_fill3(sb, 0, aH, aL, bH, bL, m0, n0, 0, tid);
    CP_COMMIT;

    const int NCH = HID / 32;   // 36
    for (int ch = 0; ch < NCH; ch++) {
        const int s = ch & 1;
        if (ch + 1 < NCH) {
            gemm_fill3(sb, s ^ 1, aH, aL, bH, bL, m0, n0, (ch + 1) * 32, tid);
            CP_COMMIT;
            CP_WAIT1;
        } else {
            CP_WAIT0;
        }
        __syncthreads();

        const uint32_t aBh = sb + s * GSTAGE + GOFF_AH;
        const uint32_t aBl = sb + s * GSTAGE + GOFF_AL;
        const uint32_t bBh = sb + s * GSTAGE + GOFF_BH;
        const uint32_t bBl = sb + s * GSTAGE + GOFF_BL;

#pragma unroll
        for (int ks = 0; ks < 2; ks++) {
            uint32_t fah[2][4], fal[2][4];
#pragma unroll
            for (int mt = 0; mt < 2; mt++) {
                uint32_t ao = a4inv + (uint32_t)((wm * 32 + mt * 16) * 80 + ks * 32);
                ldsm4(fah[mt], aBh + ao);
                ldsm4(fal[mt], aBl + ao);
            }
#pragma unroll
            for (int ntp = 0; ntp < 4; ntp++) {
                uint32_t bo = b4inv + (uint32_t)(ks * 16 * 272
                                                 + (wn * 64 + ntp * 16) * 2);
                uint32_t fbh[4], fbl[4];
                ldsm4t(fbh, bBh + bo);
                ldsm4t(fbl, bBl + bo);
#pragma unroll
                for (int mt = 0; mt < 2; mt++) {
                    mma16816(c[mt][2 * ntp],     fah[mt], fbh);
                    mma16816(c[mt][2 * ntp + 1], fah[mt], fbh + 2);
                    mma16816(c[mt][2 * ntp],     fah[mt], fbl);
                    mma16816(c[mt][2 * ntp + 1], fah[mt], fbl + 2);
                    mma16816(c[mt][2 * ntp],     fal[mt], fbh);
                    mma16816(c[mt][2 * ntp + 1], fal[mt], fbh + 2);
                }
            }
        }
        __syncthreads();
    }

#pragma unroll
    for (int mt = 0; mt < 2; mt++) {
#pragma unroll
        for (int nt = 0; nt < 8; nt++) {
            int row = m0 + wm * 32 + mt * 16 + (lane >> 2);
            int col = n0 + wn * 64 + nt * 8 + (lane & 3) * 2;
            *(float2*)(C + (size_t)row * HID + col) =
                make_float2(c[mt][nt][0], c[mt][nt][1]);
            *(float2*)(C + (size_t)(row + 8) * HID + col) =
                make_float2(c[mt][nt][2], c[mt][nt][3]);
        }
    }
}

// ============== 1-product MMA GEMM (V/O projections), K-chunk 64 ============
#define G1_A 0
#define G1_B 18432
#define G1STAGE 35840
#define GEMM1_SMEM (2*G1STAGE)

__device__ __forceinline__ void gemm_fill1(uint32_t sb, int s,
    const __half* __restrict__ aH, const __half* __restrict__ bH,
    int m0, int n0, int k0, int tid)
{
    uint32_t st = sb + s * G1STAGE;
#pragma unroll
    for (int rep = 0; rep < 4; rep++) {
        int i = tid + rep * 256;          // 0..1023
        {   // A: 128 rows x 8 16B-chunks
            int r = i >> 3, c = i & 7;
            uint32_t off = (uint32_t)(r * 144 + c * 16);
            size_t g = (size_t)(m0 + r) * HID + k0 + c * 8;
            cpa16(st + G1_A + off, aH + g);
        }
        {   // B: 64 rows x 16 chunks
            int r = i >> 4, c = i & 15;
            uint32_t off = (uint32_t)(r * 272 + c * 16);
            size_t g = (size_t)(k0 + r) * HID + n0 + c * 8;
            cpa16(st + G1_B + off, bH + g);
        }
    }
}

__global__ __launch_bounds__(256, 2)
void mma_gemm_1p(const __half* __restrict__ aH,
                 const __half* __restrict__ wH,
                 float* __restrict__ C)
{
    const int m0 = blockIdx.y * 128, n0 = blockIdx.x * 128;
    extern __shared__ char smem[];
    const uint32_t sb = smem_u32(smem);
    const int tid = threadIdx.x;
    const int lane = tid & 31;
    const int wid = tid >> 5;
    const int wm = wid & 3;
    const int wn = wid >> 2;
    const int g = lane >> 3, j = lane & 7;

    const uint32_t a4inv = (uint32_t)(((g & 1) * 8 + j) * 144 + (g >> 1) * 16);
    const uint32_t b4inv = (uint32_t)((lane & 15) * 272 + (lane >> 4) * 16);

    float c[2][8][4];
#pragma unroll
    for (int mt = 0; mt < 2; mt++)
#pragma unroll
        for (int nt = 0; nt < 8; nt++)
#pragma unroll
            for (int e = 0; e < 4; e++) c[mt][nt][e] = 0.f;

    gemm_fill1(sb, 0, aH, wH, m0, n0, 0, tid);
    CP_COMMIT;

    const int NCH = HID / 64;   // 18
    for (int ch = 0; ch < NCH; ch++) {
        const int s = ch & 1;
        if (ch + 1 < NCH) {
            gemm_fill1(sb, s ^ 1, aH, wH, m0, n0, (ch + 1) * 64, tid);
            CP_COMMIT;
            CP_WAIT1;
        } else {
            CP_WAIT0;
        }
        __syncthreads();

        const uint32_t aB = sb + s * G1STAGE + G1_A;
        const uint32_t bB = sb + s * G1STAGE + G1_B;

#pragma unroll
        for (int ks = 0; ks < 4; ks++) {
            uint32_t fah[2][4];
#pragma unroll
            for (int mt = 0; mt < 2; mt++) {
                uint32_t ao = a4inv + (uint32_t)((wm * 32 + mt * 16) * 144 + ks * 32);
                ldsm4(fah[mt], aB + ao);
            }
#pragma unroll
            for (int ntp = 0; ntp < 4; ntp++) {
                uint32_t bo = b4inv + (uint32_t)(ks * 16 * 272
                                                 + (wn * 64 + ntp * 16) * 2);
                uint32_t fbh[4];
                ldsm4t(fbh, bB + bo);
#pragma unroll
                for (int mt = 0; mt < 2; mt++) {
                    mma16816(c[mt][2 * ntp],     fah[mt], fbh);
                    mma16816(c[mt][2 * ntp + 1], fah[mt], fbh + 2);
                }
            }
        }
        __syncthreads();
    }

#pragma unroll
    for (int mt = 0; mt < 2; mt++) {
#pragma unroll
        for (int nt = 0; nt < 8; nt++) {
            int row = m0 + wm * 32 + mt * 16 + (lane >> 2);
            int col = n0 + wn * 64 + nt * 8 + (lane & 3) * 2;
            *(float2*)(C + (size_t)row * HID + col) =
                make_float2(c[mt][nt][0], c[mt][nt][1]);
            *(float2*)(C + (size_t)(row + 8) * HID + col) =
                make_float2(c[mt][nt][2], c[mt][nt][3]);
        }
    }
}

// ------------- fused RMSNorm (+weight) + 2D RoPE + fp16 hi/lo split ---------
// q is additionally scaled by LOG2E so attention softmax can use exp2.
__global__ void norm_rope_split(const float* __restrict__ q, const float* __restrict__ k,
                                const float* __restrict__ v,
                                const float* __restrict__ cosb,
                                const float* __restrict__ sinb,
                                const float* __restrict__ qw,
                                const float* __restrict__ kw,
                                __half* __restrict__ qh, __half* __restrict__ ql,
                                __half* __restrict__ kh, __half* __restrict__ kl,
                                __half* __restrict__ vh)
{
    __shared__ float sm[8][HD];
    int warp = threadIdx.x >> 5;
    int lane = threadIdx.x & 31;
    int gid = blockIdx.x * 8 + warp;
    int bp = gid >> 4;
    int h  = gid & 15;
    size_t base  = (size_t)bp * HID + (size_t)h * HD;
    size_t cbase = (size_t)bp * HD;

    float c0 = cosb[cbase + lane],      s0 = sinb[cbase + lane];
    float c1 = cosb[cbase + 32 + lane], s1 = sinb[cbase + 32 + lane];
    float c2 = 0.f, s2 = 0.f;
    if (lane < 8) { c2 = cosb[cbase + 64 + lane]; s2 = sinb[cbase + 64 + lane]; }

#pragma unroll
    for (int t = 0; t < 2; t++) {
        const float* buf = (t == 0) ? q : k;
        const float* w = (t == 0) ? qw : kw;
        __half* oh = (t == 0) ? qh : kh;
        __half* ol = (t == 0) ? ql : kl;
        const float osc = (t == 0) ? LOG2E : 1.0f;
        float x0 = buf[base + lane];
        float x1 = buf[base + 32 + lane];
        float x2 = (lane < 8) ? buf[base + 64 + lane] : 0.f;
        float ss = x0 * x0 + x1 * x1 + x2 * x2;
#pragma unroll
        for (int m = 16; m; m >>= 1) ss += __shfl_xor_sync(0xffffffffu, ss, m);
        float r = rsqrtf(ss * (1.0f / 72.0f) + 1e-6f);
        sm[warp][lane]      = x0 * r * w[lane];
        sm[warp][lane + 32] = x1 * r * w[lane + 32];
        if (lane < 8) sm[warp][lane + 64] = x2 * r * w[lane + 64];
        __syncwarp();
        {
            int d = lane;
            int jj = (d < 36) ? d : d - 36;
            float rh = (jj < 18) ? -sm[warp][d + 18] : sm[warp][d - 18];
            float out = (sm[warp][d] * c0 + rh * s0) * osc;
            __half hh = __float2half_rn(out);
            oh[base + d] = hh;
            ol[base + d] = __float2half_rn(out - __half2float(hh));
        }
        {
            int d = lane + 32;
            int jj = (d < 36) ? d : d - 36;
            float rh = (jj < 18) ? -sm[warp][d + 18] : sm[warp][d - 18];
            float out = (sm[warp][d] * c1 + rh * s1) * osc;
            __half hh = __float2half_rn(out);
            oh[base + d] = hh;
            ol[base + d] = __float2half_rn(out - __half2float(hh));
        }
        if (lane < 8) {
            int d = lane + 64;
            int jj = d - 36;
            float rh = (jj < 18) ? -sm[warp][d + 18] : sm[warp][d - 18];
            float out = (sm[warp][d] * c2 + rh * s2) * osc;
            __half hh = __float2half_rn(out);
            oh[base + d] = hh;
            ol[base + d] = __float2half_rn(out - __half2float(hh));
        }
        __syncwarp();
    }
    {
        float x0 = v[base + lane];
        float x1 = v[base + 32 + lane];
        float x2 = (lane < 8) ? v[base + 64 + lane] : 0.f;
        float ss = x0 * x0 + x1 * x1 + x2 * x2;
#pragma unroll
        for (int m = 16; m; m >>= 1) ss += __shfl_xor_sync(0xffffffffu, ss, m);
        float r = rsqrtf(ss * (1.0f / 72.0f) + 1e-6f);
        vh[base + lane]      = __float2half_rn(x0 * r);
        vh[base + 32 + lane] = __float2half_rn(x1 * r);
        if (lane < 8) vh[base + 64 + lane] = __float2half_rn(x2 * r);
    }
}

// ---------------- pipelined flash attention (mma.sync fp16) -----------------
// S is in log2 domain (q pre-scaled by LOG2E) -> softmax uses exp2f.
// QK: fp16x3 with fused tail. PV: P_hi x V_hi.
// 3-stage cp.async, ONE __syncthreads per tile.
#define AOFF_KH 0
#define AOFF_KL 11264
#define AOFF_VH 22528
#define ASTAGE  31744
#define ATTN_SMEM (3*ASTAGE)

__device__ __forceinline__ void attn_fill(uint32_t sb, int s,
    const __half* __restrict__ kh, const __half* __restrict__ kl,
    const __half* __restrict__ vh,
    size_t kb, size_t hoff, int tid)
{
    uint32_t st = sb + s * ASTAGE;
    for (int i = tid; i < 576; i += 256) {
        int r = i / 9, c = i - r * 9;
        size_t g = (kb + r) * HID + hoff + c * 8;
        uint32_t ko = (uint32_t)(r * 176 + c * 16);
        uint32_t vo = (uint32_t)(r * 144 + c * 16);
        cpa16(st + AOFF_KH + ko, kh + g);
        cpa16(st + AOFF_KL + ko, kl + g);
        cpa16(st + AOFF_VH + vo, vh + g);
    }
}

__global__ __launch_bounds__(256, 2)
void attn_mma(const __half* __restrict__ qh, const __half* __restrict__ ql,
              const __half* __restrict__ kh, const __half* __restrict__ kl,
              const __half* __restrict__ vh,
              __half* __restrict__ oh)
{
    extern __shared__ char smem[];
    const uint32_t sb = smem_u32(smem);
    const int tid = threadIdx.x;
    const int lane = tid & 31;
    const int wid = tid >> 5;
    const int b = blockIdx.z, h = blockIdx.y;
    const int q0 = blockIdx.x * 128;
    const size_t rowbase = (size_t)b * PP;
    const size_t hoff = (size_t)h * HD;

    attn_fill(sb, 0, kh, kl, vh, rowbase, hoff, tid);
    CP_COMMIT;
    attn_fill(sb, 1, kh, kl, vh, rowbase + 64, hoff, tid);
    CP_COMMIT;

    const int lg = lane >> 3, lj = lane & 7;
    const uint32_t k4inv = (uint32_t)(((lg >> 1) * 8 + lj) * 176 + (lg & 1) * 16);
    const uint32_t kt4inv = (uint32_t)((lg * 8 + lj) * 176 + 128);
    const uint32_t vinv  = (uint32_t)((lane & 15) * 144 + (lane >> 4) * 16);
    const uint32_t v2inv = (uint32_t)((lane & 15) * 144);

    uint32_t qfh[4][4], qfl[4][4], qt[4];
    {
        int ra = q0 + wid * 16 + (lane >> 2);
        const size_t ga = (rowbase + ra) * HID + hoff;
        const size_t gb = ga + (size_t)8 * HID;
        const int kof = (lane & 3) * 2;
#pragma unroll
        for (int ks = 0; ks < 4; ks++) {
            int kk = ks * 16 + kof;
            qfh[ks][0] = *(const uint32_t*)(qh + ga + kk);
            qfh[ks][1] = *(const uint32_t*)(qh + gb + kk);
            qfh[ks][2] = *(const uint32_t*)(qh + ga + kk + 8);
            qfh[ks][3] = *(const uint32_t*)(qh + gb + kk + 8);
            qfl[ks][0] = *(const uint32_t*)(ql + ga + kk);
            qfl[ks][1] = *(const uint32_t*)(ql + gb + kk);
            qfl[ks][2] = *(const uint32_t*)(ql + ga + kk + 8);
            qfl[ks][3] = *(const uint32_t*)(ql + gb + kk + 8);
        }
        qt[0] = *(const uint32_t*)(qh + ga + 64 + kof);
        qt[1] = *(const uint32_t*)(qh + gb + 64 + kof);
        qt[2] = *(const uint32_t*)(ql + ga + 64 + kof);
        qt[3] = *(const uint32_t*)(ql + gb + 64 + kof);
    }

    float m0 = -1e30f, m1 = -1e30f, l0 = 0.f, l1 = 0.f;
    float oacc[9][4];
#pragma unroll
    for (int dt = 0; dt < 9; dt++)
#pragma unroll
        for (int e = 0; e < 4; e++) oacc[dt][e] = 0.f;

    int scur = 0, snext = 2;
    const int NT = PP / 64;      // 64
    for (int kt = 0; kt < NT; kt++) {
        if (kt + 1 < NT) { CP_WAIT1; } else { CP_WAIT0; }
        __syncthreads();
        if (kt + 2 < NT) {
            attn_fill(sb, snext, kh, kl, vh,
                      rowbase + (size_t)(kt + 2) * 64, hoff, tid);
            CP_COMMIT;
        }

        const uint32_t kBh = sb + scur * ASTAGE + AOFF_KH;
        const uint32_t kBl = sb + scur * ASTAGE + AOFF_KL;
        const uint32_t vBh = sb + scur * ASTAGE + AOFF_VH;
        scur = (scur == 2) ? 0 : scur + 1;
        snext = (snext == 2) ? 0 : snext + 1;

        float sv[8][4];
#pragma unroll
        for (int nt = 0; nt < 8; nt++)
#pragma unroll
            for (int e = 0; e < 4; e++) sv[nt][e] = 0.f;

#pragma unroll
        for (int ks = 0; ks < 4; ks++) {
#pragma unroll
            for (int ntp = 0; ntp < 4; ntp++) {
                uint32_t off = k4inv + (uint32_t)(ntp * 16 * 176 + ks * 32);
                uint32_t fbh[4], fbl[4];
                ldsm4(fbh, kBh + off);
                ldsm4(fbl, kBl + off);
                mma16816(sv[2 * ntp],     qfh[ks], fbh);
                mma16816(sv[2 * ntp + 1], qfh[ks], fbh + 2);
                mma16816(sv[2 * ntp],     qfh[ks], fbl);
                mma16816(sv[2 * ntp + 1], qfh[ks], fbl + 2);
                mma16816(sv[2 * ntp],     qfl[ks], fbh);
                mma16816(sv[2 * ntp + 1], qfl[ks], fbh + 2);
            }
        }
#pragma unroll
        for (int nt0 = 0; nt0 < 8; nt0 += 4) {
            uint32_t off = kt4inv + (uint32_t)(nt0 * 8 * 176);
            uint32_t bh[4], bl[4];
            ldsm4(bh, kBh + off);
            ldsm4(bl, kBl + off);
#pragma unroll
            for (int i = 0; i < 4; i++) {
                uint32_t bb[2] = { bh[i], bh[i] };
                mma16816(sv[nt0 + i], qt, bb);
                mma16808(sv[nt0 + i], qt, bl[i]);
            }
        }

        float mx0 = -1e30f, mx1 = -1e30f;
#pragma unroll
        for (int nt = 0; nt < 8; nt++) {
            mx0 = fmaxf(mx0, fmaxf(sv[nt][0], sv[nt][1]));
            mx1 = fmaxf(mx1, fmaxf(sv[nt][2], sv[nt][3]));
        }
        mx0 = fmaxf(mx0, __shfl_xor_sync(0xffffffffu, mx0, 1));
        mx0 = fmaxf(mx0, __shfl_xor_sync(0xffffffffu, mx0, 2));
        mx1 = fmaxf(mx1, __shfl_xor_sync(0xffffffffu, mx1, 1));
        mx1 = fmaxf(mx1, __shfl_xor_sync(0xffffffffu, mx1, 2));
        float nm0 = fmaxf(m0, mx0), nm1 = fmaxf(m1, mx1);
        uint32_t changed = __ballot_sync(0xffffffffu,
                                         (nm0 != m0) || (nm1 != m1));
        float rs0 = 0.f, rs1 = 0.f;
#pragma unroll
        for (int nt = 0; nt < 8; nt++) {
            sv[nt][0] = exp2f(sv[nt][0] - nm0);
            sv[nt][1] = exp2f(sv[nt][1] - nm0);
            sv[nt][2] = exp2f(sv[nt][2] - nm1);
            sv[nt][3] = exp2f(sv[nt][3] - nm1);
            rs0 += sv[nt][0] + sv[nt][1];
            rs1 += sv[nt][2] + sv[nt][3];
        }
        if (changed) {
            float a0 = exp2f(m0 - nm0), a1 = exp2f(m1 - nm1);
            l0 = l0 * a0 + rs0;
            l1 = l1 * a1 + rs1;
#pragma unroll
            for (int dt = 0; dt < 9; dt++) {
                oacc[dt][0] *= a0; oacc[dt][1] *= a0;
                oacc[dt][2] *= a1; oacc[dt][3] *= a1;
            }
        } else {
            l0 += rs0;
            l1 += rs1;
        }
        m0 = nm0; m1 = nm1;

#pragma unroll
        for (int pk = 0; pk < 4; pk++) {
            uint32_t aph[4];
            aph[0] = pack_h2(sv[2 * pk][0],     sv[2 * pk][1]);
            aph[1] = pack_h2(sv[2 * pk][2],     sv[2 * pk][3]);
            aph[2] = pack_h2(sv[2 * pk + 1][0], sv[2 * pk + 1][1]);
            aph[3] = pack_h2(sv[2 * pk + 1][2], sv[2 * pk + 1][3]);
            const uint32_t rowoff = (uint32_t)(pk * 16 * 144);
#pragma unroll
            for (int dtp = 0; dtp < 4; dtp++) {
                uint32_t off = vinv + rowoff + (uint32_t)(dtp * 32);
                uint32_t fh[4];
                ldsm4t(fh, vBh + off);
                mma16816(oacc[2 * dtp],     aph, fh);
                mma16816(oacc[2 * dtp + 1], aph, fh + 2);
            }
            {
                uint32_t off = v2inv + rowoff + 128;
                uint32_t fh2[2];
                ldsm2t(fh2, vBh + off);
                mma16816(oacc[8], aph, fh2);
            }
        }
    }

    l0 += __shfl_xor_sync(0xffffffffu, l0, 1);
    l0 += __shfl_xor_sync(0xffffffffu, l0, 2);
    l1 += __shfl_xor_sync(0xffffffffu, l1, 1);
    l1 += __shfl_xor_sync(0xffffffffu, l1, 2);
    float il0 = 1.0f / l0, il1 = 1.0f / l1;
    int ra = q0 + wid * 16 + (lane >> 2);
    size_t ga = (rowbase + ra) * HID + hoff + (lane & 3) * 2;
    size_t gb = ga + (size_t)8 * HID;
#pragma unroll
    for (int dt = 0; dt < 9; dt++) {
        *(uint32_t*)(oh + ga + dt * 8) =
            pack_h2(oacc[dt][0] * il0, oacc[dt][1] * il0);
        *(uint32_t*)(oh + gb + dt * 8) =
            pack_h2(oacc[dt][2] * il1, oacc[dt][3] * il1);
    }
}

// ---------------------------------- launch ----------------------------------
extern "C" void kernel_launch(void* const* d_in, const int* in_sizes, int n_in,
                              void* d_out, int out_size)
{
    const float* hidden = (const float*)d_in[0];
    const float* cosb   = (const float*)d_in[1];
    const float* sinb   = (const float*)d_in[2];
    const float* Wq     = (const float*)d_in[3];
    const float* Wk     = (const float*)d_in[4];
    const float* Wv     = (const float*)d_in[5];
    const float* Wo     = (const float*)d_in[6];
    const float* qw     = (const float*)d_in[7];
    const float* kw     = (const float*)d_in[8];
    float* out = (float*)d_out;

    float *q, *k, *v;
    __half *hh, *hl, *qh, *ql, *kh, *kl, *vh;
    __half *wqh, *wql, *wkh, *wkl, *wvh, *woh, *scr;
    cudaGetSymbolAddress((void**)&q, g_q);
    cudaGetSymbolAddress((void**)&k, g_k);
    cudaGetSymbolAddress((void**)&v, g_v);
    cudaGetSymbolAddress((void**)&hh, g_hh);
    cudaGetSymbolAddress((void**)&hl, g_hl);
    cudaGetSymbolAddress((void**)&qh, g_qh);
    cudaGetSymbolAddress((void**)&ql, g_ql);
    cudaGetSymbolAddress((void**)&kh, g_kh);
    cudaGetSymbolAddress((void**)&kl, g_kl);
    cudaGetSymbolAddress((void**)&vh, g_vh);
    cudaGetSymbolAddress((void**)&wqh, g_wqh);
    cudaGetSymbolAddress((void**)&wql, g_wql);
    cudaGetSymbolAddress((void**)&wkh, g_wkh);
    cudaGetSymbolAddress((void**)&wkl, g_wkl);
    cudaGetSymbolAddress((void**)&wvh, g_wvh);
    cudaGetSymbolAddress((void**)&woh, g_woh);
    cudaGetSymbolAddress((void**)&scr, g_scr);

    cudaFuncSetAttribute(mma_gemm_qk, cudaFuncAttributeMaxDynamicSharedMemorySize,
                         GEMM_SMEM);
    cudaFuncSetAttribute(mma_gemm_1p, cudaFuncAttributeMaxDynamicSharedMemorySize,
                         GEMM1_SMEM);
    cudaFuncSetAttribute(attn_mma, cudaFuncAttributeMaxDynamicSharedMemorySize,
                         ATTN_SMEM);

    const int NH4 = (MTOT * HID) / 4;
    const int NW4 = (HID * HID) / 4;

    split_kernel<<<NH4 / 256, 256>>>(hidden, hh, hl, NH4);
    dim3 wsgrid(NW4 / 256, 4);
    split4_kernel<<<wsgrid, 256>>>(Wq, Wk, Wv, Wo,
                                   wqh, wkh, wvh, woh,
                                   wql, wkl, scr, scr, NW4);

    dim3 qkgrid(HID / 128, MTOT / 128, 2);
    mma_gemm_qk<<<qkgrid, 256, GEMM_SMEM>>>(hh, hl, wqh, wql, wkh, wkl, q, k);

    dim3 vgrid(HID / 128, MTOT / 128);
    mma_gemm_1p<<<vgrid, 256, GEMM1_SMEM>>>(hh, wvh, v);

    norm_rope_split<<<(BB * PP * NH) / 8, 256>>>(q, k, v, cosb, sinb, qw, kw,
                                                 qh, ql, kh, kl, vh);

    dim3 agrid(PP / 128, NH, BB);
    attn_mma<<<agrid, 256, ATTN_SMEM>>>(qh, ql, kh, kl, vh, hh);

    dim3 ogrid(HID / 128, MTOT / 128);
    mma_gemm_1p<<<ogrid, 256, GEMM1_SMEM>>>(hh, woh, out);
}